// round 14
// baseline (speedup 1.0000x reference)
#include <cuda_runtime.h>
#include <cstdint>

// 9-DoF alignment. Warp-specialized producer/consumer with LARGE TMA bulk
// copies: 12KB per request (whole batch tile per array) to maximize DRAM
// burst length and minimize concurrent request streams (~888 streams of
// 12KB extents vs ~7000 streams of 1.5KB in prior cp.async designs).
//
// CTA = 288 threads: warps 0-7 consume, warp 8 produces.
// 3-slot ring x 24KB (12KB x + 12KB y). Producer runs up to 3 batches ahead.
// Consumer warp w reduces points [128w, 128w+128); cross-warp combine via
// double-buffered smem scratch; warp 0 runs the 3x3 polar tail.

#define SLOT_BYTES 24576
#define X_HALF     12288
#define NSLOT      3
#define CTA_SMEM   (NSLOT * SLOT_BYTES)   // 73728B dynamic

__device__ __forceinline__ void mbar_init(uint32_t mbar, uint32_t count) {
    asm volatile("mbarrier.init.shared::cta.b64 [%0], %1;"
                 :: "r"(mbar), "r"(count) : "memory");
}
__device__ __forceinline__ void mbar_expect_tx(uint32_t mbar, uint32_t bytes) {
    asm volatile("mbarrier.arrive.expect_tx.shared::cta.b64 _, [%0], %1;"
                 :: "r"(mbar), "r"(bytes) : "memory");
}
__device__ __forceinline__ void mbar_arrive(uint32_t mbar) {
    asm volatile("mbarrier.arrive.shared::cta.b64 _, [%0];"
                 :: "r"(mbar) : "memory");
}
__device__ __forceinline__ void bulk_ld(uint32_t dst, const void* src,
                                        uint32_t bytes, uint32_t mbar) {
    asm volatile("cp.async.bulk.shared::cta.global.mbarrier::complete_tx::bytes"
                 " [%0], [%1], %2, [%3];"
                 :: "r"(dst), "l"(src), "r"(bytes), "r"(mbar) : "memory");
}
__device__ __forceinline__ void mbar_wait(uint32_t mbar, uint32_t parity) {
    uint32_t done;
    asm volatile(
        "{\n\t.reg .pred p;\n\t"
        "mbarrier.try_wait.parity.acquire.cta.shared::cta.b64 p, [%1], %2;\n\t"
        "selp.b32 %0, 1, 0, p;\n\t}"
        : "=r"(done) : "r"(mbar), "r"(parity) : "memory");
    if (!done) {
        asm volatile(
            "{\n\t.reg .pred P1;\n\t"
            "WL_%=:\n\t"
            "mbarrier.try_wait.parity.acquire.cta.shared::cta.b64 P1, [%0], %1, 0x989680;\n\t"
            "@P1 bra.uni WD_%=;\n\t"
            "bra.uni WL_%=;\n\t"
            "WD_%=:\n\t}"
            :: "r"(mbar), "r"(parity) : "memory");
    }
}

__global__ __launch_bounds__(288, 3)
void align9dof_kernel(const float* __restrict__ x,
                      const float* __restrict__ mu_x,
                      const float* __restrict__ y,
                      const float* __restrict__ mu_y,
                      float* __restrict__ out,
                      int B)
{
    extern __shared__ char slots[];
    __shared__ uint64_t mbar_store[2 * NSLOT];       // full[0..2], empty[3..5]
    __shared__ float    scratch[2][8][11];           // double-buffered partials

    const int tid  = threadIdx.x;
    const int warp = tid >> 5;
    const int lane = tid & 31;
    const int G    = gridDim.x;
    const int c    = blockIdx.x;
    const int nb   = (B - 1 - c) / G + 1;            // batches for this CTA

    const uint32_t mb0   = (uint32_t)__cvta_generic_to_shared(mbar_store);
    const uint32_t sbase = (uint32_t)__cvta_generic_to_shared(slots);
    auto full_mb  = [&](int i) { return mb0 + i * 8; };
    auto empty_mb = [&](int i) { return mb0 + (NSLOT + i) * 8; };

    if (tid == 0) {
#pragma unroll
        for (int i = 0; i < NSLOT; i++) {
            mbar_init(full_mb(i), 1);    // completed by expect_tx + tx bytes
            mbar_init(empty_mb(i), 8);   // 8 consumer-warp arrivals
        }
        asm volatile("fence.proxy.async.shared::cta;" ::: "memory");
    }
    __syncthreads();

    if (warp == 8) {
        // ---- Producer: issue whole-batch 12KB bulk loads, up to 3 ahead ----
        if (lane == 0) {
            for (int s = 0; s < nb; s++) {
                const int slot = s % NSLOT;
                const int k    = s / NSLOT;
                if (s >= NSLOT) mbar_wait(empty_mb(slot), (k - 1) & 1);
                mbar_expect_tx(full_mb(slot), SLOT_BYTES);
                const size_t b = (size_t)c + (size_t)s * G;
                bulk_ld(sbase + slot * SLOT_BYTES,
                        (const char*)x + b * 12288, X_HALF, full_mb(slot));
                bulk_ld(sbase + slot * SLOT_BYTES + X_HALF,
                        (const char*)y + b * 12288, X_HALF, full_mb(slot));
            }
        }
        return;
    }

    // ---- Consumers: warps 0-7 ----
    for (int s = 0; s < nb; s++) {
        const int slot = s % NSLOT;
        const int k    = s / NSLOT;
        const int b    = c + s * G;

        const float mx0 = mu_x[b * 3 + 0];
        const float mx1 = mu_x[b * 3 + 1];
        const float mx2 = mu_x[b * 3 + 2];
        const float my0 = mu_y[b * 3 + 0];
        const float my1 = mu_y[b * 3 + 1];
        const float my2 = mu_y[b * 3 + 2];

        mbar_wait(full_mb(slot), k & 1);

        // Warp w's slice: points [128w, 128w+128). Lane: 4 points via 3 LDS.128.
        const float4* fx = (const float4*)(slots + slot * SLOT_BYTES) + warp * 96;
        const float4* fy = (const float4*)(slots + slot * SLOT_BYTES + X_HALF) + warp * 96;

        const float4 xa = fx[3 * lane + 0];
        const float4 xm = fx[3 * lane + 1];
        const float4 xc = fx[3 * lane + 2];
        const float4 ya = fy[3 * lane + 0];
        const float4 ym = fy[3 * lane + 1];
        const float4 yc = fy[3 * lane + 2];

        const float px[4][3] = {{xa.x, xa.y, xa.z}, {xa.w, xm.x, xm.y},
                                {xm.z, xm.w, xc.x}, {xc.y, xc.z, xc.w}};
        const float py[4][3] = {{ya.x, ya.y, ya.z}, {ya.w, ym.x, ym.y},
                                {ym.z, ym.w, yc.x}, {yc.y, yc.z, yc.w}};

        float v[11];
#pragma unroll
        for (int i = 0; i < 11; i++) v[i] = 0.0f;

#pragma unroll
        for (int p = 0; p < 4; p++) {
            const float u0 = px[p][0] - mx0, u1 = px[p][1] - mx1, u2 = px[p][2] - mx2;
            const float w0 = py[p][0] - my0, w1 = py[p][1] - my1, w2 = py[p][2] - my2;
            v[0] = fmaf(u0, w0, v[0]); v[1] = fmaf(u0, w1, v[1]); v[2] = fmaf(u0, w2, v[2]);
            v[3] = fmaf(u1, w0, v[3]); v[4] = fmaf(u1, w1, v[4]); v[5] = fmaf(u1, w2, v[5]);
            v[6] = fmaf(u2, w0, v[6]); v[7] = fmaf(u2, w1, v[7]); v[8] = fmaf(u2, w2, v[8]);
            v[9]  = fmaf(u0, u0, fmaf(u1, u1, fmaf(u2, u2, v[9])));
            v[10] = fmaf(w0, w0, fmaf(w1, w1, fmaf(w2, w2, v[10])));
        }

        // Intra-warp butterfly
#pragma unroll
        for (int off = 16; off > 0; off >>= 1) {
#pragma unroll
            for (int i = 0; i < 11; i++)
                v[i] += __shfl_xor_sync(0xFFFFFFFFu, v[i], off);
        }
        if (lane == 0) {
#pragma unroll
            for (int i = 0; i < 11; i++) scratch[s & 1][warp][i] = v[i];
        }

        // All consumer warps done reading slot + scratch written
        asm volatile("bar.sync 1, 256;" ::: "memory");
        if (lane == 0) mbar_arrive(empty_mb(slot));   // slot reusable now

        if (warp == 0) {
            // ---- Final combine + polar tail (other warps advance freely) ----
            float A[9], sxx = 0.0f, syy = 0.0f;
#pragma unroll
            for (int i = 0; i < 9; i++) A[i] = 0.0f;
#pragma unroll
            for (int w = 0; w < 8; w++) {
#pragma unroll
                for (int i = 0; i < 9; i++) A[i] += scratch[s & 1][w][i];
                sxx += scratch[s & 1][w][9];
                syy += scratch[s & 1][w][10];
            }

            float fro2 = 0.0f;
#pragma unroll
            for (int i = 0; i < 9; i++) fro2 = fmaf(A[i], A[i], fro2);
            const float invf = rsqrtf(fmaxf(fro2, 1e-30f));

            float X[9];
#pragma unroll
            for (int i = 0; i < 9; i++) X[i] = A[i] * invf;

#pragma unroll
            for (int it = 0; it < 8; it++) {
                float C[9];  // cofactors: X^{-T} = C / det
                C[0] = X[4] * X[8] - X[5] * X[7];
                C[1] = X[5] * X[6] - X[3] * X[8];
                C[2] = X[3] * X[7] - X[4] * X[6];
                C[3] = X[2] * X[7] - X[1] * X[8];
                C[4] = X[0] * X[8] - X[2] * X[6];
                C[5] = X[1] * X[6] - X[0] * X[7];
                C[6] = X[1] * X[5] - X[2] * X[4];
                C[7] = X[2] * X[3] - X[0] * X[5];
                C[8] = X[0] * X[4] - X[1] * X[3];
                float det = X[0] * C[0] + X[1] * C[1] + X[2] * C[2];
                float ad  = fmaxf(fabsf(det), 1e-30f);
                float eta = rcbrtf(ad);            // |det|^{-1/3}
                float k1  = 0.5f * eta;
                float k2  = 0.5f / (eta * det);    // keeps det's sign
#pragma unroll
                for (int i = 0; i < 9; i++) X[i] = k1 * X[i] + k2 * C[i];
            }

            const float t0 = my0 - (X[0] * mx0 + X[1] * mx1 + X[2] * mx2);
            const float t1 = my1 - (X[3] * mx0 + X[4] * mx1 + X[5] * mx2);
            const float t2 = my2 - (X[6] * mx0 + X[7] * mx1 + X[8] * mx2);
            const float sf = sqrtf(syy) / (sqrtf(sxx) + 1e-6f);

            if (lane < 9) {
                float r = (lane == 0) ? X[0] :
                          (lane == 1) ? X[1] :
                          (lane == 2) ? X[2] :
                          (lane == 3) ? X[3] :
                          (lane == 4) ? X[4] :
                          (lane == 5) ? X[5] :
                          (lane == 6) ? X[6] :
                          (lane == 7) ? X[7] : X[8];
                out[(size_t)b * 9 + lane] = r;
            }
            if (lane < 3) {
                float tv = (lane == 0) ? t0 : (lane == 1) ? t1 : t2;
                out[(size_t)B * 9 + (size_t)b * 3 + lane] = tv;
            }
            if (lane == 0) {
                out[(size_t)B * 12 + b] = sf;
            }
        }
    }
}

extern "C" void kernel_launch(void* const* d_in, const int* in_sizes, int n_in,
                              void* d_out, int out_size)
{
    const float* x    = (const float*)d_in[0];
    const float* mu_x = (const float*)d_in[1];
    const float* y    = (const float*)d_in[2];
    const float* mu_y = (const float*)d_in[3];
    float* out        = (float*)d_out;

    const int B = in_sizes[1] / 3;  // mu_x is [B,3]

    cudaFuncSetAttribute(align9dof_kernel,
                         cudaFuncAttributeMaxDynamicSharedMemorySize, CTA_SMEM);

    int grid = 148 * 3;             // persistent: 3 CTAs per SM
    if (grid > B) grid = B;

    align9dof_kernel<<<grid, 288, CTA_SMEM>>>(x, mu_x, y, mu_y, out, B);
}